// round 13
// baseline (speedup 1.0000x reference)
#include <cuda_runtime.h>
#include <math.h>
#include <stdint.h>

#define B_ 8
#define S_ 128
#define T_ 24
#define E_ 512
#define H_ 512
#define L_ 256
#define H3_ 1536
#define D_ 2048
#define PAD_ 516

typedef unsigned long long ull;

// ------------------------------ device scratch ------------------------------
__device__ float g_x[2][B_*S_][E_];
__device__ float g_gi[2][B_][S_][H3_];
__device__ float g_henc[2][2][B_*H_];       // [gru][buf]
__device__ float g_enc_out[B_][L_][H_];
__device__ float g_enc_proj[B_][L_][H_];
__device__ float g_enc_dot[B_][L_];
__device__ float g_hid0[B_][H_];
__device__ float g_hidbuf[2][B_][H_];
__device__ float g_edec[B_][T_][E_];
__device__ float g_gie[B_][T_][H3_];
__device__ float g_weffp[32][D_];
__device__ float g_weff[D_];
__device__ float g_beff[1];
__device__ float g_q[B_][H_];
__device__ float g_scores[B_][L_];
__device__ float g_wall[T_][B_][H_];
__device__ float g_h2all[T_][B_][H_];

// barrier state: ids 0,1 = encoder GRUs; 2 = decoder full; 8+b = decoder group b
__device__ unsigned g_cnt[512];
__device__ unsigned g_gen[512];

__device__ __forceinline__ float sigm(float x) { return 1.0f / (1.0f + expf(-x)); }

__device__ __forceinline__ float warp_sum(float v) {
#pragma unroll
    for (int off = 16; off; off >>= 1) v += __shfl_down_sync(0xffffffffu, v, off);
    return v;
}

// ---- packed f32x2 helpers (sm_103a) ----
__device__ __forceinline__ void fma2(ull& d, ull a, ull b) {
    asm("fma.rn.f32x2 %0, %1, %2, %0;" : "+l"(d) : "l"(a), "l"(b));
}
__device__ __forceinline__ float fhadd(ull v) {
    float lo, hi;
    asm("mov.b64 {%0, %1}, %2;" : "=f"(lo), "=f"(hi) : "l"(v));
    return lo + hi;
}

// ---- grid barrier: single acq_rel atomic arrival + release-store broadcast ----
__device__ __forceinline__ void gbar(int id, unsigned n, unsigned target) {
    __threadfence();
    __syncthreads();
    if (threadIdx.x == 0) {
        unsigned old;
        asm volatile("atom.acq_rel.gpu.global.add.u32 %0, [%1], 1;"
                     : "=r"(old) : "l"(&g_cnt[id * 32]) : "memory");
        if (old == n - 1u) {
            g_cnt[id * 32] = 0;
            asm volatile("st.release.gpu.global.u32 [%0], %1;"
                         :: "l"(&g_gen[id * 32]), "r"(target) : "memory");
        } else {
            unsigned v;
            do {
                asm volatile("ld.acquire.gpu.global.u32 %0, [%1];"
                             : "=r"(v) : "l"(&g_gen[id * 32]) : "memory");
            } while ((int)(v - target) < 0);
        }
    }
    __syncthreads();
}

// ---------- fused init + embedding gathers (single launch) ----------
__global__ void k_prep(const int* __restrict__ pre, const int* __restrict__ post,
                       const int* __restrict__ trg, const float* __restrict__ emb) {
    int blk = blockIdx.x;
    if (blk < 2048) {
        int g = blk >> 10;
        int bs = blk & 1023;
        int tok = (g ? post : pre)[bs];
        const float4* src = (const float4*)(emb + (size_t)tok * E_);
        float4* dst = (float4*)(&g_x[g][bs][0]);
        dst[threadIdx.x] = src[threadIdx.x];
    } else if (blk < 2048 + B_ * T_) {
        int r = blk - 2048;
        int b = r / T_, t = r % T_;
        int tok = (t == 0) ? pre[b * S_ + S_ - 1] : trg[b * T_ + t - 1];
        const float4* src = (const float4*)(emb + (size_t)tok * E_);
        float4* dst = (float4*)(&g_edec[b][t][0]);
        dst[threadIdx.x] = src[threadIdx.x];
    } else {
        for (int i = threadIdx.x; i < 512; i += 128) { g_cnt[i] = 0; g_gen[i] = 0; }
    }
}

// --------------- scalar GEMM body: C[M,N] = A[M,K] @ W[N,K]^T + bias ---------------
__device__ __forceinline__ void gemm_body(const float* __restrict__ A, int lda,
                                          const float* __restrict__ W, int ldw,
                                          const float* __restrict__ bias,
                                          float* __restrict__ C, int ldc, int K,
                                          int m0, int n0) {
    __shared__ float As[16][68];
    __shared__ float Ws[16][68];
    int tid = threadIdx.x;
    int tx = tid & 15, ty = tid >> 4;
    int lr = tid >> 2;
    int lk = (tid & 3) * 4;
    float acc[4][4] = {};
    for (int k0 = 0; k0 < K; k0 += 16) {
        float4 av = *(const float4*)&A[(size_t)(m0 + lr) * lda + k0 + lk];
        float4 wv = *(const float4*)&W[(size_t)(n0 + lr) * ldw + k0 + lk];
        __syncthreads();
        As[lk + 0][lr] = av.x; As[lk + 1][lr] = av.y; As[lk + 2][lr] = av.z; As[lk + 3][lr] = av.w;
        Ws[lk + 0][lr] = wv.x; Ws[lk + 1][lr] = wv.y; Ws[lk + 2][lr] = wv.z; Ws[lk + 3][lr] = wv.w;
        __syncthreads();
#pragma unroll
        for (int kk = 0; kk < 16; kk++) {
            float4 a4 = *(const float4*)&As[kk][ty * 4];
            float4 w4 = *(const float4*)&Ws[kk][tx * 4];
            acc[0][0] = fmaf(a4.x, w4.x, acc[0][0]); acc[0][1] = fmaf(a4.x, w4.y, acc[0][1]);
            acc[0][2] = fmaf(a4.x, w4.z, acc[0][2]); acc[0][3] = fmaf(a4.x, w4.w, acc[0][3]);
            acc[1][0] = fmaf(a4.y, w4.x, acc[1][0]); acc[1][1] = fmaf(a4.y, w4.y, acc[1][1]);
            acc[1][2] = fmaf(a4.y, w4.z, acc[1][2]); acc[1][3] = fmaf(a4.y, w4.w, acc[1][3]);
            acc[2][0] = fmaf(a4.z, w4.x, acc[2][0]); acc[2][1] = fmaf(a4.z, w4.y, acc[2][1]);
            acc[2][2] = fmaf(a4.z, w4.z, acc[2][2]); acc[2][3] = fmaf(a4.z, w4.w, acc[2][3]);
            acc[3][0] = fmaf(a4.w, w4.x, acc[3][0]); acc[3][1] = fmaf(a4.w, w4.y, acc[3][1]);
            acc[3][2] = fmaf(a4.w, w4.z, acc[3][2]); acc[3][3] = fmaf(a4.w, w4.w, acc[3][3]);
        }
    }
    float4 b4 = *(const float4*)&bias[n0 + tx * 4];
#pragma unroll
    for (int i = 0; i < 4; i++) {
        float4 o = make_float4(acc[i][0] + b4.x, acc[i][1] + b4.y,
                               acc[i][2] + b4.z, acc[i][3] + b4.w);
        *(float4*)&C[(size_t)(m0 + ty * 4 + i) * ldc + n0 + tx * 4] = o;
    }
}

__global__ __launch_bounds__(256) void k_gemm(const float* __restrict__ A, int lda,
                                              const float* __restrict__ W, int ldw,
                                              const float* __restrict__ bias,
                                              float* __restrict__ C, int ldc, int K) {
    gemm_body(A, lda, W, ldw, bias, C, ldc, K, blockIdx.y * 64, blockIdx.x * 64);
}

__global__ __launch_bounds__(256) void k_gemm2(const float* __restrict__ A0, const float* __restrict__ W0,
                                               const float* __restrict__ b0, float* __restrict__ C0,
                                               const float* __restrict__ A1, const float* __restrict__ W1,
                                               const float* __restrict__ b1, float* __restrict__ C1) {
    const float* A = blockIdx.z ? A1 : A0;
    const float* W = blockIdx.z ? W1 : W0;
    const float* bias = blockIdx.z ? b1 : b0;
    float* C = blockIdx.z ? C1 : C0;
    gemm_body(A, E_, W, E_, bias, C, H3_, E_, blockIdx.y * 64, blockIdx.x * 64);
}

// ------------- w_eff two-stage -------------
__global__ void k_weffp(const float* __restrict__ fcW, const float* __restrict__ outW) {
    int j4 = (blockIdx.x & 3) * 128 + threadIdx.x;
    int kb = blockIdx.x >> 2;
    float4 acc = make_float4(0.f, 0.f, 0.f, 0.f);
    for (int i = kb * 64; i < kb * 64 + 64; i++) {
        float ov = __ldg(&outW[i]);
        float4 w = *(const float4*)&fcW[(size_t)i * D_ + j4 * 4];
        acc.x = fmaf(ov, w.x, acc.x); acc.y = fmaf(ov, w.y, acc.y);
        acc.z = fmaf(ov, w.z, acc.z); acc.w = fmaf(ov, w.w, acc.w);
    }
    *(float4*)&g_weffp[kb][j4 * 4] = acc;
}

__global__ void k_weff2(const float* __restrict__ outW, const float* __restrict__ fcb,
                        const float* __restrict__ outb) {
    int j = blockIdx.x * 256 + threadIdx.x;
    float v = 0.f;
#pragma unroll
    for (int kb = 0; kb < 32; kb++) v += g_weffp[kb][j];
    g_weff[j] = v;
    if (blockIdx.x == 0) {
        __shared__ float red[256];
        float a = 0.f;
        for (int i = threadIdx.x; i < D_; i += 256) a = fmaf(outW[i], fcb[i], a);
        red[threadIdx.x] = a; __syncthreads();
        for (int off = 128; off; off >>= 1) {
            if (threadIdx.x < off) red[threadIdx.x] += red[threadIdx.x + off];
            __syncthreads();
        }
        if (threadIdx.x == 0) g_beff[0] = outb[0] + red[0];
    }
}

// ------------------ persistent encoder: all 128 GRU steps ------------------
__global__ __launch_bounds__(256)
void k_enc(const float* __restrict__ Whh_pre, const float* __restrict__ bhh_pre,
           const float* __restrict__ Whh_post, const float* __restrict__ bhh_post) {
    extern __shared__ float sm[];
    float* wsm  = sm;                          // [3][8][PAD_]
    float* hs   = sm + 3 * 8 * PAD_;           // [8][PAD_]
    float* part = hs + 8 * PAD_;               // [3][8][8][4]
    int g = blockIdx.x >> 6, blk = blockIdx.x & 63;
    const float* Whh = g ? Whh_post : Whh_pre;
    const float* bhh = g ? bhh_post : bhh_pre;
    int t = threadIdx.x, b = t & 7, jl = (t >> 3) & 7, ks = t >> 6;
    int j = blk * 8 + jl;

    for (int i = t; i < 3 * 8 * 512; i += 256) {
        int gate = i >> 12, rem = i & 4095, jj = rem >> 9, k = rem & 511;
        wsm[(gate * 8 + jj) * PAD_ + k] = Whh[((size_t)(gate * 512 + blk * 8 + jj)) * 512 + k];
    }
    for (int i = t; i < 8 * PAD_; i += 256) hs[i] = 0.0f;
    float br = 0.f, bz = 0.f, bn = 0.f;
    if (ks == 0) { br = bhh[j]; bz = bhh[512 + j]; bn = bhh[1024 + j]; }
    __syncthreads();

    for (int s = 0; s < S_; s++) {
        float gir = 0.f, giz = 0.f, gin = 0.f;
        if (ks == 0) {
            gir = __ldg(&g_gi[g][b][s][j]);
            giz = __ldg(&g_gi[g][b][s][512 + j]);
            gin = __ldg(&g_gi[g][b][s][1024 + j]);
        }
        const ulonglong2* hb = (const ulonglong2*)&hs[b * PAD_ + ks * 128];
        const ulonglong2* wr = (const ulonglong2*)&wsm[(0 * 8 + jl) * PAD_ + ks * 128];
        const ulonglong2* wz = (const ulonglong2*)&wsm[(1 * 8 + jl) * PAD_ + ks * 128];
        const ulonglong2* wn = (const ulonglong2*)&wsm[(2 * 8 + jl) * PAD_ + ks * 128];
        ull ar2 = 0, az2 = 0, an2 = 0;
#pragma unroll 8
        for (int k = 0; k < 32; k++) {
            ulonglong2 h2 = hb[k];
            ulonglong2 r2 = wr[k], z2 = wz[k], n2 = wn[k];
            fma2(ar2, h2.x, r2.x); fma2(ar2, h2.y, r2.y);
            fma2(az2, h2.x, z2.x); fma2(az2, h2.y, z2.y);
            fma2(an2, h2.x, n2.x); fma2(an2, h2.y, n2.y);
        }
        part[((0 * 8 + jl) * 8 + b) * 4 + ks] = fhadd(ar2);
        part[((1 * 8 + jl) * 8 + b) * 4 + ks] = fhadd(az2);
        part[((2 * 8 + jl) * 8 + b) * 4 + ks] = fhadd(an2);
        __syncthreads();
        if (ks == 0) {
            float* p0 = &part[((0 * 8 + jl) * 8 + b) * 4];
            float* p1 = &part[((1 * 8 + jl) * 8 + b) * 4];
            float* p2 = &part[((2 * 8 + jl) * 8 + b) * 4];
            float ghr = p0[0] + p0[1] + p0[2] + p0[3] + br;
            float ghz = p1[0] + p1[1] + p1[2] + p1[3] + bz;
            float ghn = p2[0] + p2[1] + p2[2] + p2[3] + bn;
            float r = sigm(gir + ghr);
            float z = sigm(giz + ghz);
            float n = tanhf(gin + r * ghn);
            float h2 = (1.0f - z) * n + z * hs[b * PAD_ + j];
            __stcg(&g_henc[g][s & 1][b * 512 + j], h2);
            g_enc_out[b][g * 128 + s][j] = h2;
        }
        gbar(g, 64, (unsigned)(s + 1));
        const float4* src = (const float4*)&g_henc[g][s & 1][0];
        for (int i = t; i < 1024; i += 256) {
            float4 v = __ldcg(src + i);
            int base = i * 4;
            float* d = &hs[(base >> 9) * PAD_ + (base & 511)];
            d[0] = v.x; d[1] = v.y; d[2] = v.z; d[3] = v.w;
        }
        __syncthreads();
    }
}

// -------- hidden0 = tanh([pre_h|post_h] @ fc_enc_W^T + b) --------
__global__ __launch_bounds__(256) void k_hidden(const float* __restrict__ W,
                                                const float* __restrict__ bias) {
    __shared__ float hcat[8][1028];
    int t = threadIdx.x;
    for (int i = t; i < 8 * 1024; i += 256) {
        int b = i >> 10, k = i & 1023;
        hcat[b][k] = (k < 512) ? g_henc[0][1][b * 512 + k] : g_henc[1][1][b * 512 + k - 512];
    }
    __syncthreads();
    int b = t & 7, d = blockIdx.x * 32 + (t >> 3);
    const float4* w = (const float4*)(W + (size_t)d * 1024);
    const float4* x = (const float4*)&hcat[b][0];
    float acc = 0.f;
#pragma unroll 4
    for (int k = 0; k < 256; k++) {
        float4 w4 = w[k], x4 = x[k];
        acc = fmaf(w4.x, x4.x, acc); acc = fmaf(w4.y, x4.y, acc);
        acc = fmaf(w4.z, x4.z, acc); acc = fmaf(w4.w, x4.w, acc);
    }
    g_hid0[b][d] = tanhf(acc + bias[d]);
}

// --------------- enc_dot[b][l] = enc_out[b][l] . w_eff[0:512] ---------------
__global__ void k_encdot() {
    int r = blockIdx.x * 8 + (threadIdx.x >> 5);
    int lane = threadIdx.x & 31;
    int b = r >> 8, l = r & 255;
    const float4* e = (const float4*)&g_enc_out[b][l][0];
    const float4* w = (const float4*)&g_weff[0];
    float v = 0.f;
#pragma unroll
    for (int c = 0; c < 4; c++) {
        int f = lane + 32 * c;
        float4 e4 = e[f], w4 = w[f];
        v = fmaf(e4.x, w4.x, v); v = fmaf(e4.y, w4.y, v);
        v = fmaf(e4.z, w4.z, v); v = fmaf(e4.w, w4.w, v);
    }
    v = warp_sum(v);
    if (lane == 0) g_enc_dot[b][l] = v;
}

// ------------------ persistent decoder: all 24 steps ------------------
// 128 blocks; blk -> (myb = blk>>4, hch = (blk&15)*32). Phase A computes q[myb]
// per-batch so A->B and B->C need only the 16-CTA group barrier.
__global__ __launch_bounds__(256)
void k_dec(const float* __restrict__ Wih, const float* __restrict__ Whh,
           const float* __restrict__ bhh, const float* __restrict__ attnW,
           const float* __restrict__ attnv) {
    extern __shared__ float sm[];
    float* whh_sm  = sm;                              // [3][4][PAD_]
    float* wih_sm  = whh_sm + 3 * 4 * PAD_;           // [3][4][PAD_]
    float* whid32  = wih_sm + 3 * 4 * PAD_;           // [32][512]
    float* hs      = whid32 + 32 * 512;               // [8][PAD_]
    float* ws      = hs + 8 * PAD_;                   // [8][PAD_]
    float* ep_sm   = ws + 8 * PAD_;                   // [16][512]
    float* eo_sm   = ep_sm + 16 * 512;                // [256][33]
    float* vs_sm   = eo_sm + 256 * 33;                // [512]
    float* q_sm    = vs_sm + 512;                     // [512]
    float* red     = q_sm + 512;                      // [256]
    float* aa      = red + 256;                       // [256]
    float* part    = aa + 256;                        // [1536]
    int t = threadIdx.x;
    int blk = blockIdx.x;
    int b8 = t & 7, jl4 = (t >> 3) & 3, ks8 = t >> 5;
    int myb = blk >> 4, hch = (blk & 15) * 32;
    int j = blk * 4 + jl4;

    for (int i = t; i < 3 * 4 * 512; i += 256) {
        int gate = i >> 11, rem = i & 2047, jj = rem >> 9, k = rem & 511;
        int row = gate * 512 + blk * 4 + jj;
        whh_sm[(gate * 4 + jj) * PAD_ + k] = Whh[(size_t)row * 512 + k];
        wih_sm[(gate * 4 + jj) * PAD_ + k] = Wih[(size_t)row * 1024 + 512 + k];
    }
    for (int i = t; i < 32 * 512; i += 256)
        whid32[i] = attnW[(size_t)(hch + (i >> 9)) * 1024 + (i & 511)];
    for (int i = t; i < 8 * 512; i += 256)
        hs[(i >> 9) * PAD_ + (i & 511)] = ((const float*)g_hid0)[i];
    for (int i = t; i < 16 * 512; i += 256) {
        int row = i >> 9, f = i & 511;
        int r = blk * 16 + row, bb = r >> 8, l = r & 255;
        ep_sm[i] = g_enc_proj[bb][l][f];
    }
    for (int i = t; i < 256 * 32; i += 256) {
        int l = i >> 5, hh = i & 31;
        eo_sm[l * 33 + hh] = g_enc_out[myb][l][hch + hh];
    }
    for (int i = t; i < 512; i += 256) vs_sm[i] = attnv[i];
    float bhr = 0.f, bhz = 0.f, bhn = 0.f;
    if (ks8 == 0) { bhr = bhh[j]; bhz = bhh[512 + j]; bhn = bhh[1024 + j]; }
    __syncthreads();

    unsigned genF = 0, genG = 0;
    for (int tt = 0; tt < T_; tt++) {
        float gir = 0.f, giz = 0.f, gin = 0.f;
        if (ks8 == 0) {
            gir = __ldg(&g_gie[b8][tt][j]);
            giz = __ldg(&g_gie[b8][tt][512 + j]);
            gin = __ldg(&g_gie[b8][tt][1024 + j]);
        }
        // ---- A: q[myb][hch+dl] = hs[myb] . W_hid[hch+dl] ----
        {
            int dl = t >> 3, ksA = t & 7;              // 32 dims x 8 k-slices
            const float4* wd = (const float4*)&whid32[dl * 512 + ksA * 64];
            const float4* hb4 = (const float4*)&hs[myb * PAD_ + ksA * 64];
            float acc = 0.f;
#pragma unroll
            for (int k = 0; k < 16; k++) {
                float4 w4 = wd[k], h4 = hb4[k];
                acc = fmaf(w4.x, h4.x, acc); acc = fmaf(w4.y, h4.y, acc);
                acc = fmaf(w4.z, h4.z, acc); acc = fmaf(w4.w, h4.w, acc);
            }
            part[dl * 8 + ksA] = acc;
            __syncthreads();
            if (t < 32) {
                float* p = &part[t * 8];
                __stcg(&g_q[myb][hch + t],
                       p[0] + p[1] + p[2] + p[3] + p[4] + p[5] + p[6] + p[7]);
            }
        }
        genG++; gbar(8 + myb, 16, genG);   // q[myb] complete (group)
        // ---- B: scores; stage full q[myb] into smem ----
        {
            for (int i = t; i < 128; i += 256) {
                float4 v = __ldcg(((const float4*)&g_q[myb][0]) + i);
                *(float4*)&q_sm[i * 4] = v;
            }
            __syncthreads();
            int w = t >> 5, lane = t & 31;
#pragma unroll
            for (int rr = 0; rr < 2; rr++) {
                int row = w * 2 + rr;
                int r = blk * 16 + row;
                int bb = r >> 8, l = r & 255;
                const float4* ep = (const float4*)&ep_sm[row * 512];
                const float4* qp = (const float4*)q_sm;
                const float4* vp = (const float4*)vs_sm;
                float acc = 0.f;
#pragma unroll
                for (int c = 0; c < 4; c++) {
                    int f = lane + 32 * c;
                    float4 e4 = ep[f], v4 = vp[f], q4 = qp[f];
                    acc = fmaf(tanhf(e4.x + q4.x), v4.x, acc);
                    acc = fmaf(tanhf(e4.y + q4.y), v4.y, acc);
                    acc = fmaf(tanhf(e4.z + q4.z), v4.z, acc);
                    acc = fmaf(tanhf(e4.w + q4.w), v4.w, acc);
                }
                acc = warp_sum(acc);
                if (lane == 0) { __stcg(&g_scores[bb][l], acc); }
            }
        }
        genG++; gbar(8 + myb, 16, genG);   // scores[myb] complete (group)
        // ---- C: softmax over L for myb + weighted chunk ----
        {
            float s = __ldcg(&g_scores[myb][t]);
            red[t] = s; __syncthreads();
            for (int off = 128; off; off >>= 1) {
                if (t < off) red[t] = fmaxf(red[t], red[t + off]);
                __syncthreads();
            }
            float mx = red[0]; __syncthreads();
            float e = expf(s - mx);
            red[t] = e; __syncthreads();
            for (int off = 128; off; off >>= 1) {
                if (t < off) red[t] += red[t + off];
                __syncthreads();
            }
            aa[t] = e / red[0];
            __syncthreads();
            int hh = t & 31, ls = t >> 5;
            float acc = 0.f;
            int l0 = ls * 32;
#pragma unroll 8
            for (int l = l0; l < l0 + 32; l++)
                acc = fmaf(aa[l], eo_sm[l * 33 + hh], acc);
            part[ls * 32 + hh] = acc;
            __syncthreads();
            if (t < 32) {
                float v = 0.f;
#pragma unroll
                for (int q = 0; q < 8; q++) v += part[q * 32 + t];
                __stcg(&g_wall[tt][myb][hch + t], v);
            }
        }
        genF++; gbar(2, 128, genF);        // weighted for all batches (full)
        // ---- D: GRU ----
        {
            const float4* src = (const float4*)&g_wall[tt][0][0];
            for (int i = t; i < 1024; i += 256) {
                float4 v = __ldcg(src + i);
                int base = i * 4;
                float* d = &ws[(base >> 9) * PAD_ + (base & 511)];
                d[0] = v.x; d[1] = v.y; d[2] = v.z; d[3] = v.w;
            }
            __syncthreads();
            const ulonglong2* hb = (const ulonglong2*)&hs[b8 * PAD_ + ks8 * 64];
            const ulonglong2* wb = (const ulonglong2*)&ws[b8 * PAD_ + ks8 * 64];
            const ulonglong2* whr = (const ulonglong2*)&whh_sm[(0 * 4 + jl4) * PAD_ + ks8 * 64];
            const ulonglong2* whz = (const ulonglong2*)&whh_sm[(1 * 4 + jl4) * PAD_ + ks8 * 64];
            const ulonglong2* whn = (const ulonglong2*)&whh_sm[(2 * 4 + jl4) * PAD_ + ks8 * 64];
            const ulonglong2* wir = (const ulonglong2*)&wih_sm[(0 * 4 + jl4) * PAD_ + ks8 * 64];
            const ulonglong2* wiz = (const ulonglong2*)&wih_sm[(1 * 4 + jl4) * PAD_ + ks8 * 64];
            const ulonglong2* win = (const ulonglong2*)&wih_sm[(2 * 4 + jl4) * PAD_ + ks8 * 64];
            ull ahr = 0, ahz = 0, ahn = 0, air = 0, aiz = 0, ain = 0;
#pragma unroll 4
            for (int k = 0; k < 16; k++) {
                ulonglong2 h2 = hb[k], w2 = wb[k];
                ulonglong2 r2 = whr[k], z2 = whz[k], n2 = whn[k];
                ulonglong2 a2 = wir[k], c2 = wiz[k], d2 = win[k];
                fma2(ahr, h2.x, r2.x); fma2(ahr, h2.y, r2.y);
                fma2(ahz, h2.x, z2.x); fma2(ahz, h2.y, z2.y);
                fma2(ahn, h2.x, n2.x); fma2(ahn, h2.y, n2.y);
                fma2(air, w2.x, a2.x); fma2(air, w2.y, a2.y);
                fma2(aiz, w2.x, c2.x); fma2(aiz, w2.y, c2.y);
                fma2(ain, w2.x, d2.x); fma2(ain, w2.y, d2.y);
            }
            part[(0 * 4 + jl4) * 64 + b8 * 8 + ks8] = fhadd(ahr);
            part[(1 * 4 + jl4) * 64 + b8 * 8 + ks8] = fhadd(ahz);
            part[(2 * 4 + jl4) * 64 + b8 * 8 + ks8] = fhadd(ahn);
            part[(3 * 4 + jl4) * 64 + b8 * 8 + ks8] = fhadd(air);
            part[(4 * 4 + jl4) * 64 + b8 * 8 + ks8] = fhadd(aiz);
            part[(5 * 4 + jl4) * 64 + b8 * 8 + ks8] = fhadd(ain);
            __syncthreads();
            if (ks8 == 0) {
                float sum[6];
#pragma unroll
                for (int m = 0; m < 6; m++) {
                    float* p = &part[(m * 4 + jl4) * 64 + b8 * 8];
                    sum[m] = p[0] + p[1] + p[2] + p[3] + p[4] + p[5] + p[6] + p[7];
                }
                float ghr = sum[0] + bhr, ghz = sum[1] + bhz, ghn = sum[2] + bhn;
                float r = sigm((gir + sum[3]) + ghr);
                float z = sigm((giz + sum[4]) + ghz);
                float n = tanhf((gin + sum[5]) + r * ghn);
                float h2 = (1.0f - z) * n + z * hs[b8 * PAD_ + j];
                __stcg(&g_hidbuf[(tt + 1) & 1][b8][j], h2);
                g_h2all[tt][b8][j] = h2;
            }
        }
        genF++; gbar(2, 128, genF);        // h2 for all batches (full)
        if (tt + 1 < T_) {
            const float4* src = (const float4*)&g_hidbuf[(tt + 1) & 1][0][0];
            for (int i = t; i < 1024; i += 256) {
                float4 v = __ldcg(src + i);
                int base = i * 4;
                float* d = &hs[(base >> 9) * PAD_ + (base & 511)];
                d[0] = v.x; d[1] = v.y; d[2] = v.z; d[3] = v.w;
            }
            __syncthreads();
        }
    }
}

// ------------------------------ final logits ------------------------------
__global__ void k_logits(float* __restrict__ out) {
    int b = blockIdx.x / T_, tt = blockIdx.x % T_;
    int t = threadIdx.x;
    __shared__ float red[256];
    float acc = 0.f;
#pragma unroll
    for (int c = 0; c < 2; c++) {
        int h = t + c * 256;
        acc = fmaf(g_wall[tt][b][h],  g_weff[512 + h],  acc);
        acc = fmaf(g_h2all[tt][b][h], g_weff[1024 + h], acc);
        acc = fmaf(g_edec[b][tt][h],  g_weff[1536 + h], acc);
    }
    red[t] = acc; __syncthreads();
    for (int off = 128; off; off >>= 1) {
        if (t < off) red[t] += red[t + off];
        __syncthreads();
    }
    float sc = red[0] + g_beff[0];
    float val = g_enc_dot[b][t] + sc;
    int base = (b * T_ + tt) * 128;
    if (t < 128) out[base + t] = val;
    else out[B_ * T_ * 128 + base + t - 128] = val;
}

// ------------------------------ host launch ------------------------------
extern "C" void kernel_launch(void* const* d_in, const int* in_sizes, int n_in,
                              void* d_out, int out_size) {
    const int*   pre      = (const int*)d_in[0];
    const int*   post     = (const int*)d_in[1];
    const int*   trg      = (const int*)d_in[2];
    const float* emb      = (const float*)d_in[3];
    const float* Wih_pre  = (const float*)d_in[4];
    const float* Whh_pre  = (const float*)d_in[5];
    const float* bih_pre  = (const float*)d_in[6];
    const float* bhh_pre  = (const float*)d_in[7];
    const float* Wih_post = (const float*)d_in[8];
    const float* Whh_post = (const float*)d_in[9];
    const float* bih_post = (const float*)d_in[10];
    const float* bhh_post = (const float*)d_in[11];
    const float* fc_enc_W = (const float*)d_in[12];
    const float* fc_enc_b = (const float*)d_in[13];
    const float* attn_W   = (const float*)d_in[14];
    const float* attn_b   = (const float*)d_in[15];
    const float* attn_v   = (const float*)d_in[16];
    const float* Wih_dec  = (const float*)d_in[17];
    const float* Whh_dec  = (const float*)d_in[18];
    const float* bih_dec  = (const float*)d_in[19];
    const float* bhh_dec  = (const float*)d_in[20];
    const float* fc_hid_W = (const float*)d_in[21];
    const float* fc_hid_b = (const float*)d_in[22];
    const float* fc_out_W = (const float*)d_in[23];
    const float* fc_out_b = (const float*)d_in[24];
    float* out = (float*)d_out;

    float *p_x, *p_gi, *p_edec, *p_gie, *p_enc_out, *p_enc_proj;
    cudaGetSymbolAddress((void**)&p_x, g_x);
    cudaGetSymbolAddress((void**)&p_gi, g_gi);
    cudaGetSymbolAddress((void**)&p_edec, g_edec);
    cudaGetSymbolAddress((void**)&p_gie, g_gie);
    cudaGetSymbolAddress((void**)&p_enc_out, g_enc_out);
    cudaGetSymbolAddress((void**)&p_enc_proj, g_enc_proj);

    const int ENC_SMEM = (3 * 8 * PAD_ + 8 * PAD_ + 768) * 4;
    const int DEC_SMEM = (3 * 4 * PAD_ * 2 + 32 * 512 + 8 * PAD_ * 2 +
                          16 * 512 + 256 * 33 + 512 + 512 + 256 + 256 + 1536) * 4;
    cudaFuncSetAttribute(k_enc, cudaFuncAttributeMaxDynamicSharedMemorySize, ENC_SMEM);
    cudaFuncSetAttribute(k_dec, cudaFuncAttributeMaxDynamicSharedMemorySize, DEC_SMEM);

    // launch order: k_enc is our 4th launch (the ncu capture slot)
    k_prep<<<2048 + B_ * T_ + 1, 128>>>(pre, post, trg, emb);        // 1
    k_gemm2<<<dim3(24, 16, 2), 256>>>(p_x, Wih_pre, bih_pre, p_gi,   // 2
                                      p_x + (size_t)B_ * S_ * E_, Wih_post, bih_post,
                                      p_gi + (size_t)B_ * S_ * H3_);
    k_gemm<<<dim3(24, 3), 256>>>(p_edec, E_, Wih_dec, 1024, bih_dec, // 3
                                 p_gie, H3_, E_);
    k_enc<<<128, 256, ENC_SMEM>>>(Whh_pre, bhh_pre, Whh_post, bhh_post);  // 4 <- profiled

    k_weffp<<<128, 128>>>(fc_hid_W, fc_out_W);
    k_weff2<<<8, 256>>>(fc_out_W, fc_hid_b, fc_out_b);
    k_hidden<<<16, 256>>>(fc_enc_W, fc_enc_b);
    k_gemm<<<dim3(8, 32), 256>>>(p_enc_out, H_, attn_W + H_, 1024, attn_b, p_enc_proj, H_, H_);
    k_encdot<<<256, 256>>>();

    k_dec<<<128, 256, DEC_SMEM>>>(Wih_dec, Whh_dec, bhh_dec, attn_W, attn_v);

    k_logits<<<B_ * T_, 256>>>(out);
}

// round 14
// speedup vs baseline: 1.1432x; 1.1432x over previous
#include <cuda_runtime.h>
#include <math.h>
#include <stdint.h>

#define B_ 8
#define S_ 128
#define T_ 24
#define E_ 512
#define H_ 512
#define L_ 256
#define H3_ 1536
#define D_ 2048
#define PAD_ 516

typedef unsigned long long ull;

// ------------------------------ device scratch ------------------------------
__device__ float g_x[2][B_*S_][E_];
__device__ float g_gi[2][B_][S_][H3_];
__device__ float g_henc[2][2][B_*H_];       // [gru][buf]
__device__ float g_enc_out[B_][L_][H_];
__device__ float g_enc_proj[B_][L_][H_];
__device__ float g_enc_dot[B_][L_];
__device__ float g_hid0[B_][H_];
__device__ float g_hidbuf[2][B_][H_];
__device__ float g_edec[B_][T_][E_];
__device__ float g_gie[B_][T_][H3_];
__device__ float g_weffp[32][D_];
__device__ float g_weff[D_];
__device__ float g_beff[1];
__device__ float g_q[B_][H_];
__device__ float g_scores[B_][L_];
__device__ float g_wall[T_][B_][H_];
__device__ float g_h2all[T_][B_][H_];

// barrier state: ids 0,1 = encoder GRUs; 2 = decoder full; 8+b = decoder group b
__device__ unsigned g_cnt[512];
__device__ unsigned g_gen[512];

__device__ __forceinline__ float sigm(float x) { return 1.0f / (1.0f + expf(-x)); }

__device__ __forceinline__ float warp_sum(float v) {
#pragma unroll
    for (int off = 16; off; off >>= 1) v += __shfl_down_sync(0xffffffffu, v, off);
    return v;
}

// ---- packed f32x2 helpers (sm_103a) ----
__device__ __forceinline__ void fma2(ull& d, ull a, ull b) {
    asm("fma.rn.f32x2 %0, %1, %2, %0;" : "+l"(d) : "l"(a), "l"(b));
}
__device__ __forceinline__ float fhadd(ull v) {
    float lo, hi;
    asm("mov.b64 {%0, %1}, %2;" : "=f"(lo), "=f"(hi) : "l"(v));
    return lo + hi;
}

// ---- grid barrier: single acq_rel atomic arrival + release-store broadcast ----
// No explicit __threadfence: release semantics of the arrival atom order the
// CTA's prior global stores; waiters order via ld.acquire.
__device__ __forceinline__ void gbar(int id, unsigned n, unsigned target) {
    __syncthreads();
    if (threadIdx.x == 0) {
        unsigned old;
        asm volatile("atom.acq_rel.gpu.global.add.u32 %0, [%1], 1;"
                     : "=r"(old) : "l"(&g_cnt[id * 32]) : "memory");
        if (old == n - 1u) {
            g_cnt[id * 32] = 0;
            asm volatile("st.release.gpu.global.u32 [%0], %1;"
                         :: "l"(&g_gen[id * 32]), "r"(target) : "memory");
        } else {
            unsigned v;
            do {
                asm volatile("ld.acquire.gpu.global.u32 %0, [%1];"
                             : "=r"(v) : "l"(&g_gen[id * 32]) : "memory");
            } while ((int)(v - target) < 0);
        }
    }
    __syncthreads();
}

// ---------- fused init + embedding gathers (single launch) ----------
__global__ void k_prep(const int* __restrict__ pre, const int* __restrict__ post,
                       const int* __restrict__ trg, const float* __restrict__ emb) {
    int blk = blockIdx.x;
    if (blk < 2048) {
        int g = blk >> 10;
        int bs = blk & 1023;
        int tok = (g ? post : pre)[bs];
        const float4* src = (const float4*)(emb + (size_t)tok * E_);
        float4* dst = (float4*)(&g_x[g][bs][0]);
        dst[threadIdx.x] = src[threadIdx.x];
    } else if (blk < 2048 + B_ * T_) {
        int r = blk - 2048;
        int b = r / T_, t = r % T_;
        int tok = (t == 0) ? pre[b * S_ + S_ - 1] : trg[b * T_ + t - 1];
        const float4* src = (const float4*)(emb + (size_t)tok * E_);
        float4* dst = (float4*)(&g_edec[b][t][0]);
        dst[threadIdx.x] = src[threadIdx.x];
    } else {
        for (int i = threadIdx.x; i < 512; i += 128) { g_cnt[i] = 0; g_gen[i] = 0; }
    }
}

// --------------- scalar GEMM body: C[M,N] = A[M,K] @ W[N,K]^T + bias ---------------
__device__ __forceinline__ void gemm_body(const float* __restrict__ A, int lda,
                                          const float* __restrict__ W, int ldw,
                                          const float* __restrict__ bias,
                                          float* __restrict__ C, int ldc, int K,
                                          int m0, int n0) {
    __shared__ float As[16][68];
    __shared__ float Ws[16][68];
    int tid = threadIdx.x;
    int tx = tid & 15, ty = tid >> 4;
    int lr = tid >> 2;
    int lk = (tid & 3) * 4;
    float acc[4][4] = {};
    for (int k0 = 0; k0 < K; k0 += 16) {
        float4 av = *(const float4*)&A[(size_t)(m0 + lr) * lda + k0 + lk];
        float4 wv = *(const float4*)&W[(size_t)(n0 + lr) * ldw + k0 + lk];
        __syncthreads();
        As[lk + 0][lr] = av.x; As[lk + 1][lr] = av.y; As[lk + 2][lr] = av.z; As[lk + 3][lr] = av.w;
        Ws[lk + 0][lr] = wv.x; Ws[lk + 1][lr] = wv.y; Ws[lk + 2][lr] = wv.z; Ws[lk + 3][lr] = wv.w;
        __syncthreads();
#pragma unroll
        for (int kk = 0; kk < 16; kk++) {
            float4 a4 = *(const float4*)&As[kk][ty * 4];
            float4 w4 = *(const float4*)&Ws[kk][tx * 4];
            acc[0][0] = fmaf(a4.x, w4.x, acc[0][0]); acc[0][1] = fmaf(a4.x, w4.y, acc[0][1]);
            acc[0][2] = fmaf(a4.x, w4.z, acc[0][2]); acc[0][3] = fmaf(a4.x, w4.w, acc[0][3]);
            acc[1][0] = fmaf(a4.y, w4.x, acc[1][0]); acc[1][1] = fmaf(a4.y, w4.y, acc[1][1]);
            acc[1][2] = fmaf(a4.y, w4.z, acc[1][2]); acc[1][3] = fmaf(a4.y, w4.w, acc[1][3]);
            acc[2][0] = fmaf(a4.z, w4.x, acc[2][0]); acc[2][1] = fmaf(a4.z, w4.y, acc[2][1]);
            acc[2][2] = fmaf(a4.z, w4.z, acc[2][2]); acc[2][3] = fmaf(a4.z, w4.w, acc[2][3]);
            acc[3][0] = fmaf(a4.w, w4.x, acc[3][0]); acc[3][1] = fmaf(a4.w, w4.y, acc[3][1]);
            acc[3][2] = fmaf(a4.w, w4.z, acc[3][2]); acc[3][3] = fmaf(a4.w, w4.w, acc[3][3]);
        }
    }
    float4 b4 = *(const float4*)&bias[n0 + tx * 4];
#pragma unroll
    for (int i = 0; i < 4; i++) {
        float4 o = make_float4(acc[i][0] + b4.x, acc[i][1] + b4.y,
                               acc[i][2] + b4.z, acc[i][3] + b4.w);
        *(float4*)&C[(size_t)(m0 + ty * 4 + i) * ldc + n0 + tx * 4] = o;
    }
}

__global__ __launch_bounds__(256) void k_gemm(const float* __restrict__ A, int lda,
                                              const float* __restrict__ W, int ldw,
                                              const float* __restrict__ bias,
                                              float* __restrict__ C, int ldc, int K) {
    gemm_body(A, lda, W, ldw, bias, C, ldc, K, blockIdx.y * 64, blockIdx.x * 64);
}

__global__ __launch_bounds__(256) void k_gemm2(const float* __restrict__ A0, const float* __restrict__ W0,
                                               const float* __restrict__ b0, float* __restrict__ C0,
                                               const float* __restrict__ A1, const float* __restrict__ W1,
                                               const float* __restrict__ b1, float* __restrict__ C1) {
    const float* A = blockIdx.z ? A1 : A0;
    const float* W = blockIdx.z ? W1 : W0;
    const float* bias = blockIdx.z ? b1 : b0;
    float* C = blockIdx.z ? C1 : C0;
    gemm_body(A, E_, W, E_, bias, C, H3_, E_, blockIdx.y * 64, blockIdx.x * 64);
}

// ------------- w_eff two-stage -------------
__global__ void k_weffp(const float* __restrict__ fcW, const float* __restrict__ outW) {
    int j4 = (blockIdx.x & 3) * 128 + threadIdx.x;
    int kb = blockIdx.x >> 2;
    float4 acc = make_float4(0.f, 0.f, 0.f, 0.f);
    for (int i = kb * 64; i < kb * 64 + 64; i++) {
        float ov = __ldg(&outW[i]);
        float4 w = *(const float4*)&fcW[(size_t)i * D_ + j4 * 4];
        acc.x = fmaf(ov, w.x, acc.x); acc.y = fmaf(ov, w.y, acc.y);
        acc.z = fmaf(ov, w.z, acc.z); acc.w = fmaf(ov, w.w, acc.w);
    }
    *(float4*)&g_weffp[kb][j4 * 4] = acc;
}

__global__ void k_weff2(const float* __restrict__ outW, const float* __restrict__ fcb,
                        const float* __restrict__ outb) {
    int j = blockIdx.x * 256 + threadIdx.x;
    float v = 0.f;
#pragma unroll
    for (int kb = 0; kb < 32; kb++) v += g_weffp[kb][j];
    g_weff[j] = v;
    if (blockIdx.x == 0) {
        __shared__ float red[256];
        float a = 0.f;
        for (int i = threadIdx.x; i < D_; i += 256) a = fmaf(outW[i], fcb[i], a);
        red[threadIdx.x] = a; __syncthreads();
        for (int off = 128; off; off >>= 1) {
            if (threadIdx.x < off) red[threadIdx.x] += red[threadIdx.x + off];
            __syncthreads();
        }
        if (threadIdx.x == 0) g_beff[0] = outb[0] + red[0];
    }
}

// ------------------ persistent encoder: all 128 GRU steps ------------------
__global__ __launch_bounds__(256)
void k_enc(const float* __restrict__ Whh_pre, const float* __restrict__ bhh_pre,
           const float* __restrict__ Whh_post, const float* __restrict__ bhh_post) {
    extern __shared__ float sm[];
    float* wsm  = sm;                          // [3][8][PAD_]
    float* hs   = sm + 3 * 8 * PAD_;           // [8][PAD_]
    float* part = hs + 8 * PAD_;               // [3][8][8][4]
    int g = blockIdx.x >> 6, blk = blockIdx.x & 63;
    const float* Whh = g ? Whh_post : Whh_pre;
    const float* bhh = g ? bhh_post : bhh_pre;
    int t = threadIdx.x, b = t & 7, jl = (t >> 3) & 7, ks = t >> 6;
    int j = blk * 8 + jl;

    for (int i = t; i < 3 * 8 * 512; i += 256) {
        int gate = i >> 12, rem = i & 4095, jj = rem >> 9, k = rem & 511;
        wsm[(gate * 8 + jj) * PAD_ + k] = Whh[((size_t)(gate * 512 + blk * 8 + jj)) * 512 + k];
    }
    for (int i = t; i < 8 * PAD_; i += 256) hs[i] = 0.0f;
    float br = 0.f, bz = 0.f, bn = 0.f;
    if (ks == 0) { br = bhh[j]; bz = bhh[512 + j]; bn = bhh[1024 + j]; }
    __syncthreads();

    for (int s = 0; s < S_; s++) {
        float gir = 0.f, giz = 0.f, gin = 0.f;
        if (ks == 0) {
            gir = __ldg(&g_gi[g][b][s][j]);
            giz = __ldg(&g_gi[g][b][s][512 + j]);
            gin = __ldg(&g_gi[g][b][s][1024 + j]);
        }
        const ulonglong2* hb = (const ulonglong2*)&hs[b * PAD_ + ks * 128];
        const ulonglong2* wr = (const ulonglong2*)&wsm[(0 * 8 + jl) * PAD_ + ks * 128];
        const ulonglong2* wz = (const ulonglong2*)&wsm[(1 * 8 + jl) * PAD_ + ks * 128];
        const ulonglong2* wn = (const ulonglong2*)&wsm[(2 * 8 + jl) * PAD_ + ks * 128];
        ull ar2 = 0, az2 = 0, an2 = 0;
#pragma unroll 8
        for (int k = 0; k < 32; k++) {
            ulonglong2 h2 = hb[k];
            ulonglong2 r2 = wr[k], z2 = wz[k], n2 = wn[k];
            fma2(ar2, h2.x, r2.x); fma2(ar2, h2.y, r2.y);
            fma2(az2, h2.x, z2.x); fma2(az2, h2.y, z2.y);
            fma2(an2, h2.x, n2.x); fma2(an2, h2.y, n2.y);
        }
        part[((0 * 8 + jl) * 8 + b) * 4 + ks] = fhadd(ar2);
        part[((1 * 8 + jl) * 8 + b) * 4 + ks] = fhadd(az2);
        part[((2 * 8 + jl) * 8 + b) * 4 + ks] = fhadd(an2);
        __syncthreads();
        if (ks == 0) {
            float* p0 = &part[((0 * 8 + jl) * 8 + b) * 4];
            float* p1 = &part[((1 * 8 + jl) * 8 + b) * 4];
            float* p2 = &part[((2 * 8 + jl) * 8 + b) * 4];
            float ghr = p0[0] + p0[1] + p0[2] + p0[3] + br;
            float ghz = p1[0] + p1[1] + p1[2] + p1[3] + bz;
            float ghn = p2[0] + p2[1] + p2[2] + p2[3] + bn;
            float r = sigm(gir + ghr);
            float z = sigm(giz + ghz);
            float n = tanhf(gin + r * ghn);
            float h2 = (1.0f - z) * n + z * hs[b * PAD_ + j];
            __stcg(&g_henc[g][s & 1][b * 512 + j], h2);
            g_enc_out[b][g * 128 + s][j] = h2;
        }
        gbar(g, 64, (unsigned)(s + 1));
        const float4* src = (const float4*)&g_henc[g][s & 1][0];
        for (int i = t; i < 1024; i += 256) {
            float4 v = __ldcg(src + i);
            int base = i * 4;
            float* d = &hs[(base >> 9) * PAD_ + (base & 511)];
            d[0] = v.x; d[1] = v.y; d[2] = v.z; d[3] = v.w;
        }
        __syncthreads();
    }
}

// -------- hidden0 = tanh([pre_h|post_h] @ fc_enc_W^T + b) --------
__global__ __launch_bounds__(256) void k_hidden(const float* __restrict__ W,
                                                const float* __restrict__ bias) {
    __shared__ float hcat[8][1028];
    int t = threadIdx.x;
    for (int i = t; i < 8 * 1024; i += 256) {
        int b = i >> 10, k = i & 1023;
        hcat[b][k] = (k < 512) ? g_henc[0][1][b * 512 + k] : g_henc[1][1][b * 512 + k - 512];
    }
    __syncthreads();
    int b = t & 7, d = blockIdx.x * 32 + (t >> 3);
    const float4* w = (const float4*)(W + (size_t)d * 1024);
    const float4* x = (const float4*)&hcat[b][0];
    float acc = 0.f;
#pragma unroll 4
    for (int k = 0; k < 256; k++) {
        float4 w4 = w[k], x4 = x[k];
        acc = fmaf(w4.x, x4.x, acc); acc = fmaf(w4.y, x4.y, acc);
        acc = fmaf(w4.z, x4.z, acc); acc = fmaf(w4.w, x4.w, acc);
    }
    g_hid0[b][d] = tanhf(acc + bias[d]);
}

// --------------- enc_dot[b][l] = enc_out[b][l] . w_eff[0:512] ---------------
__global__ void k_encdot() {
    int r = blockIdx.x * 8 + (threadIdx.x >> 5);
    int lane = threadIdx.x & 31;
    int b = r >> 8, l = r & 255;
    const float4* e = (const float4*)&g_enc_out[b][l][0];
    const float4* w = (const float4*)&g_weff[0];
    float v = 0.f;
#pragma unroll
    for (int c = 0; c < 4; c++) {
        int f = lane + 32 * c;
        float4 e4 = e[f], w4 = w[f];
        v = fmaf(e4.x, w4.x, v); v = fmaf(e4.y, w4.y, v);
        v = fmaf(e4.z, w4.z, v); v = fmaf(e4.w, w4.w, v);
    }
    v = warp_sum(v);
    if (lane == 0) g_enc_dot[b][l] = v;
}

// ------------------ persistent decoder: all 24 steps ------------------
__global__ __launch_bounds__(256)
void k_dec(const float* __restrict__ Wih, const float* __restrict__ Whh,
           const float* __restrict__ bhh, const float* __restrict__ attnW,
           const float* __restrict__ attnv) {
    extern __shared__ float sm[];
    float* whh_sm  = sm;                              // [3][4][PAD_]
    float* wih_sm  = whh_sm + 3 * 4 * PAD_;
    float* whid_sm = wih_sm + 3 * 4 * PAD_;           // [4][PAD_]
    float* hs      = whid_sm + 4 * PAD_;              // [8][PAD_]
    float* ws      = hs + 8 * PAD_;                   // [8][PAD_]
    float* ep_sm   = ws + 8 * PAD_;                   // [16][512]
    float* eo_sm   = ep_sm + 16 * 512;                // [256][33]
    float* vs_sm   = eo_sm + 256 * 33;                // [512]
    float* q_sm    = vs_sm + 512;                     // [512]
    float* red     = q_sm + 512;                      // [256]
    float* aa      = red + 256;                       // [256]
    float* part    = aa + 256;                        // [1536]
    int t = threadIdx.x;
    int blk = blockIdx.x;
    int b8 = t & 7, jl4 = (t >> 3) & 3, ks8 = t >> 5;
    int myb = blk >> 4, hch = (blk & 15) * 32;
    int j = blk * 4 + jl4;

    for (int i = t; i < 3 * 4 * 512; i += 256) {
        int gate = i >> 11, rem = i & 2047, jj = rem >> 9, k = rem & 511;
        int row = gate * 512 + blk * 4 + jj;
        whh_sm[(gate * 4 + jj) * PAD_ + k] = Whh[(size_t)row * 512 + k];
        wih_sm[(gate * 4 + jj) * PAD_ + k] = Wih[(size_t)row * 1024 + 512 + k];
    }
    for (int i = t; i < 4 * 512; i += 256)
        whid_sm[(i >> 9) * PAD_ + (i & 511)] = attnW[(size_t)(blk * 4 + (i >> 9)) * 1024 + (i & 511)];
    for (int i = t; i < 8 * 512; i += 256)
        hs[(i >> 9) * PAD_ + (i & 511)] = ((const float*)g_hid0)[i];
    for (int i = t; i < 16 * 512; i += 256) {
        int row = i >> 9, f = i & 511;
        int r = blk * 16 + row, bb = r >> 8, l = r & 255;
        ep_sm[i] = g_enc_proj[bb][l][f];
    }
    for (int i = t; i < 256 * 32; i += 256) {
        int l = i >> 5, hh = i & 31;
        eo_sm[l * 33 + hh] = g_enc_out[myb][l][hch + hh];
    }
    for (int i = t; i < 512; i += 256) vs_sm[i] = attnv[i];
    float bhr = 0.f, bhz = 0.f, bhn = 0.f;
    if (ks8 == 0) { bhr = bhh[j]; bhz = bhh[512 + j]; bhn = bhh[1024 + j]; }
    __syncthreads();

    unsigned gen = 0;
    for (int tt = 0; tt < T_; tt++) {
        float gir = 0.f, giz = 0.f, gin = 0.f;
        if (ks8 == 0) {
            gir = __ldg(&g_gie[b8][tt][j]);
            giz = __ldg(&g_gie[b8][tt][512 + j]);
            gin = __ldg(&g_gie[b8][tt][1024 + j]);
        }
        // ---- A: q[b][d] = h . W_hid[d] ----
        {
            const ulonglong2* hb = (const ulonglong2*)&hs[b8 * PAD_ + ks8 * 64];
            const ulonglong2* wd = (const ulonglong2*)&whid_sm[jl4 * PAD_ + ks8 * 64];
            ull acc2 = 0;
#pragma unroll
            for (int k = 0; k < 16; k++) {
                ulonglong2 h2 = hb[k], w2 = wd[k];
                fma2(acc2, h2.x, w2.x); fma2(acc2, h2.y, w2.y);
            }
            part[(jl4 * 8 + b8) * 8 + ks8] = fhadd(acc2);
            __syncthreads();
            if (ks8 == 0) {
                float* p = &part[(jl4 * 8 + b8) * 8];
                __stcg(&g_q[b8][j], p[0] + p[1] + p[2] + p[3] + p[4] + p[5] + p[6] + p[7]);
            }
        }
        gen++; gbar(2, 128, gen);
        // ---- B: scores[b][l]; stage q[myb] into smem once ----
        {
            for (int i = t; i < 128; i += 256) {
                float4 v = __ldcg(((const float4*)&g_q[myb][0]) + i);
                *(float4*)&q_sm[i * 4] = v;
            }
            __syncthreads();
            int w = t >> 5, lane = t & 31;
#pragma unroll
            for (int rr = 0; rr < 2; rr++) {
                int row = w * 2 + rr;
                int r = blk * 16 + row;
                int bb = r >> 8, l = r & 255;
                const float4* ep = (const float4*)&ep_sm[row * 512];
                const float4* qp = (const float4*)q_sm;
                const float4* vp = (const float4*)vs_sm;
                float acc = 0.f;
#pragma unroll
                for (int c = 0; c < 4; c++) {
                    int f = lane + 32 * c;
                    float4 e4 = ep[f], v4 = vp[f], q4 = qp[f];
                    acc = fmaf(tanhf(e4.x + q4.x), v4.x, acc);
                    acc = fmaf(tanhf(e4.y + q4.y), v4.y, acc);
                    acc = fmaf(tanhf(e4.z + q4.z), v4.z, acc);
                    acc = fmaf(tanhf(e4.w + q4.w), v4.w, acc);
                }
                acc = warp_sum(acc);
                if (lane == 0) { __stcg(&g_scores[bb][l], acc); }
            }
        }
        gen++; gbar(8 + myb, 16, gen);
        // ---- C: softmax over L for myb + weighted chunk ----
        {
            float s = __ldcg(&g_scores[myb][t]);
            red[t] = s; __syncthreads();
            for (int off = 128; off; off >>= 1) {
                if (t < off) red[t] = fmaxf(red[t], red[t + off]);
                __syncthreads();
            }
            float mx = red[0]; __syncthreads();
            float e = expf(s - mx);
            red[t] = e; __syncthreads();
            for (int off = 128; off; off >>= 1) {
                if (t < off) red[t] += red[t + off];
                __syncthreads();
            }
            aa[t] = e / red[0];
            __syncthreads();
            int hh = t & 31, ls = t >> 5;
            float acc = 0.f;
            int l0 = ls * 32;
#pragma unroll 8
            for (int l = l0; l < l0 + 32; l++)
                acc = fmaf(aa[l], eo_sm[l * 33 + hh], acc);
            part[ls * 32 + hh] = acc;
            __syncthreads();
            if (t < 32) {
                float v = 0.f;
#pragma unroll
                for (int q = 0; q < 8; q++) v += part[q * 32 + t];
                __stcg(&g_wall[tt][myb][hch + t], v);
            }
        }
        gen++; gbar(2, 128, gen);
        // ---- D: GRU ----
        {
            const float4* src = (const float4*)&g_wall[tt][0][0];
            for (int i = t; i < 1024; i += 256) {
                float4 v = __ldcg(src + i);
                int base = i * 4;
                float* d = &ws[(base >> 9) * PAD_ + (base & 511)];
                d[0] = v.x; d[1] = v.y; d[2] = v.z; d[3] = v.w;
            }
            __syncthreads();
            const ulonglong2* hb = (const ulonglong2*)&hs[b8 * PAD_ + ks8 * 64];
            const ulonglong2* wb = (const ulonglong2*)&ws[b8 * PAD_ + ks8 * 64];
            const ulonglong2* whr = (const ulonglong2*)&whh_sm[(0 * 4 + jl4) * PAD_ + ks8 * 64];
            const ulonglong2* whz = (const ulonglong2*)&whh_sm[(1 * 4 + jl4) * PAD_ + ks8 * 64];
            const ulonglong2* whn = (const ulonglong2*)&whh_sm[(2 * 4 + jl4) * PAD_ + ks8 * 64];
            const ulonglong2* wir = (const ulonglong2*)&wih_sm[(0 * 4 + jl4) * PAD_ + ks8 * 64];
            const ulonglong2* wiz = (const ulonglong2*)&wih_sm[(1 * 4 + jl4) * PAD_ + ks8 * 64];
            const ulonglong2* win = (const ulonglong2*)&wih_sm[(2 * 4 + jl4) * PAD_ + ks8 * 64];
            ull ahr = 0, ahz = 0, ahn = 0, air = 0, aiz = 0, ain = 0;
#pragma unroll 4
            for (int k = 0; k < 16; k++) {
                ulonglong2 h2 = hb[k], w2 = wb[k];
                ulonglong2 r2 = whr[k], z2 = whz[k], n2 = whn[k];
                ulonglong2 a2 = wir[k], c2 = wiz[k], d2 = win[k];
                fma2(ahr, h2.x, r2.x); fma2(ahr, h2.y, r2.y);
                fma2(ahz, h2.x, z2.x); fma2(ahz, h2.y, z2.y);
                fma2(ahn, h2.x, n2.x); fma2(ahn, h2.y, n2.y);
                fma2(air, w2.x, a2.x); fma2(air, w2.y, a2.y);
                fma2(aiz, w2.x, c2.x); fma2(aiz, w2.y, c2.y);
                fma2(ain, w2.x, d2.x); fma2(ain, w2.y, d2.y);
            }
            part[(0 * 4 + jl4) * 64 + b8 * 8 + ks8] = fhadd(ahr);
            part[(1 * 4 + jl4) * 64 + b8 * 8 + ks8] = fhadd(ahz);
            part[(2 * 4 + jl4) * 64 + b8 * 8 + ks8] = fhadd(ahn);
            part[(3 * 4 + jl4) * 64 + b8 * 8 + ks8] = fhadd(air);
            part[(4 * 4 + jl4) * 64 + b8 * 8 + ks8] = fhadd(aiz);
            part[(5 * 4 + jl4) * 64 + b8 * 8 + ks8] = fhadd(ain);
            __syncthreads();
            if (ks8 == 0) {
                float sum[6];
#pragma unroll
                for (int m = 0; m < 6; m++) {
                    float* p = &part[(m * 4 + jl4) * 64 + b8 * 8];
                    sum[m] = p[0] + p[1] + p[2] + p[3] + p[4] + p[5] + p[6] + p[7];
                }
                float ghr = sum[0] + bhr, ghz = sum[1] + bhz, ghn = sum[2] + bhn;
                float r = sigm((gir + sum[3]) + ghr);
                float z = sigm((giz + sum[4]) + ghz);
                float n = tanhf((gin + sum[5]) + r * ghn);
                float h2 = (1.0f - z) * n + z * hs[b8 * PAD_ + j];
                __stcg(&g_hidbuf[(tt + 1) & 1][b8][j], h2);
                g_h2all[tt][b8][j] = h2;
            }
        }
        gen++; gbar(2, 128, gen);
        if (tt + 1 < T_) {
            const float4* src = (const float4*)&g_hidbuf[(tt + 1) & 1][0][0];
            for (int i = t; i < 1024; i += 256) {
                float4 v = __ldcg(src + i);
                int base = i * 4;
                float* d = &hs[(base >> 9) * PAD_ + (base & 511)];
                d[0] = v.x; d[1] = v.y; d[2] = v.z; d[3] = v.w;
            }
            __syncthreads();
        }
    }
}

// ------------------------------ final logits ------------------------------
__global__ void k_logits(float* __restrict__ out) {
    int b = blockIdx.x / T_, tt = blockIdx.x % T_;
    int t = threadIdx.x;
    __shared__ float red[256];
    float acc = 0.f;
#pragma unroll
    for (int c = 0; c < 2; c++) {
        int h = t + c * 256;
        acc = fmaf(g_wall[tt][b][h],  g_weff[512 + h],  acc);
        acc = fmaf(g_h2all[tt][b][h], g_weff[1024 + h], acc);
        acc = fmaf(g_edec[b][tt][h],  g_weff[1536 + h], acc);
    }
    red[t] = acc; __syncthreads();
    for (int off = 128; off; off >>= 1) {
        if (t < off) red[t] += red[t + off];
        __syncthreads();
    }
    float sc = red[0] + g_beff[0];
    float val = g_enc_dot[b][t] + sc;
    int base = (b * T_ + tt) * 128;
    if (t < 128) out[base + t] = val;
    else out[B_ * T_ * 128 + base + t - 128] = val;
}

// ------------------------------ host launch ------------------------------
extern "C" void kernel_launch(void* const* d_in, const int* in_sizes, int n_in,
                              void* d_out, int out_size) {
    const int*   pre      = (const int*)d_in[0];
    const int*   post     = (const int*)d_in[1];
    const int*   trg      = (const int*)d_in[2];
    const float* emb      = (const float*)d_in[3];
    const float* Wih_pre  = (const float*)d_in[4];
    const float* Whh_pre  = (const float*)d_in[5];
    const float* bih_pre  = (const float*)d_in[6];
    const float* bhh_pre  = (const float*)d_in[7];
    const float* Wih_post = (const float*)d_in[8];
    const float* Whh_post = (const float*)d_in[9];
    const float* bih_post = (const float*)d_in[10];
    const float* bhh_post = (const float*)d_in[11];
    const float* fc_enc_W = (const float*)d_in[12];
    const float* fc_enc_b = (const float*)d_in[13];
    const float* attn_W   = (const float*)d_in[14];
    const float* attn_b   = (const float*)d_in[15];
    const float* attn_v   = (const float*)d_in[16];
    const float* Wih_dec  = (const float*)d_in[17];
    const float* Whh_dec  = (const float*)d_in[18];
    const float* bih_dec  = (const float*)d_in[19];
    const float* bhh_dec  = (const float*)d_in[20];
    const float* fc_hid_W = (const float*)d_in[21];
    const float* fc_hid_b = (const float*)d_in[22];
    const float* fc_out_W = (const float*)d_in[23];
    const float* fc_out_b = (const float*)d_in[24];
    float* out = (float*)d_out;

    float *p_x, *p_gi, *p_edec, *p_gie, *p_enc_out, *p_enc_proj;
    cudaGetSymbolAddress((void**)&p_x, g_x);
    cudaGetSymbolAddress((void**)&p_gi, g_gi);
    cudaGetSymbolAddress((void**)&p_edec, g_edec);
    cudaGetSymbolAddress((void**)&p_gie, g_gie);
    cudaGetSymbolAddress((void**)&p_enc_out, g_enc_out);
    cudaGetSymbolAddress((void**)&p_enc_proj, g_enc_proj);

    const int ENC_SMEM = (3 * 8 * PAD_ + 8 * PAD_ + 768) * 4;
    const int DEC_SMEM = (3 * 4 * PAD_ * 2 + 4 * PAD_ + 8 * PAD_ * 2 +
                          16 * 512 + 256 * 33 + 512 + 512 + 256 + 256 + 1536) * 4;
    cudaFuncSetAttribute(k_enc, cudaFuncAttributeMaxDynamicSharedMemorySize, ENC_SMEM);
    cudaFuncSetAttribute(k_dec, cudaFuncAttributeMaxDynamicSharedMemorySize, DEC_SMEM);

    // launch order: k_enc is our 4th launch (the ncu capture slot)
    k_prep<<<2048 + B_ * T_ + 1, 128>>>(pre, post, trg, emb);        // 1
    k_gemm2<<<dim3(24, 16, 2), 256>>>(p_x, Wih_pre, bih_pre, p_gi,   // 2
                                      p_x + (size_t)B_ * S_ * E_, Wih_post, bih_post,
                                      p_gi + (size_t)B_ * S_ * H3_);
    k_gemm<<<dim3(24, 3), 256>>>(p_edec, E_, Wih_dec, 1024, bih_dec, // 3
                                 p_gie, H3_, E_);
    k_enc<<<128, 256, ENC_SMEM>>>(Whh_pre, bhh_pre, Whh_post, bhh_post);  // 4 <- profiled

    k_weffp<<<128, 128>>>(fc_hid_W, fc_out_W);
    k_weff2<<<8, 256>>>(fc_out_W, fc_hid_b, fc_out_b);
    k_hidden<<<16, 256>>>(fc_enc_W, fc_enc_b);
    k_gemm<<<dim3(8, 32), 256>>>(p_enc_out, H_, attn_W + H_, 1024, attn_b, p_enc_proj, H_, H_);
    k_encdot<<<256, 256>>>();

    k_dec<<<128, 256, DEC_SMEM>>>(Wih_dec, Whh_dec, bhh_dec, attn_W, attn_v);

    k_logits<<<B_ * T_, 256>>>(out);
}

// round 15
// speedup vs baseline: 1.2937x; 1.1317x over previous
#include <cuda_runtime.h>
#include <math.h>
#include <stdint.h>

#define B_ 8
#define S_ 128
#define T_ 24
#define E_ 512
#define H_ 512
#define L_ 256
#define H3_ 1536
#define D_ 2048
#define PAD_ 516

typedef unsigned long long ull;

// ------------------------------ device scratch ------------------------------
__device__ float g_x[2][B_*S_][E_];
__device__ float g_gi[2][B_][S_][H3_];
__device__ float g_henc[2][2][B_*H_];       // [gru][buf]
__device__ float g_enc_out[B_][L_][H_];
__device__ float g_enc_proj[B_][L_][H_];
__device__ float g_enc_dot[B_][L_];
__device__ float g_hid0[B_][H_];
__device__ float g_hidbuf[2][B_][H_];
__device__ float g_edec[B_][T_][E_];
__device__ float g_gie[B_][T_][H3_];
__device__ float g_weffp[32][D_];
__device__ float g_weff[D_];
__device__ float g_beff[1];
__device__ float g_q[B_][H_];
__device__ float g_scores[B_][L_];
__device__ float g_wall[T_][B_][H_];
__device__ float g_h2all[T_][B_][H_];

// barrier state: monotonically-increasing counters. ids: 0,1 = encoder GRUs;
// 2 = decoder full; 8+b = decoder group b.
__device__ unsigned g_cnt[512];

__device__ __forceinline__ float sigm(float x) { return 1.0f / (1.0f + expf(-x)); }

__device__ __forceinline__ float warp_sum(float v) {
#pragma unroll
    for (int off = 16; off; off >>= 1) v += __shfl_down_sync(0xffffffffu, v, off);
    return v;
}

// ---- packed f32x2 helpers (sm_103a) ----
__device__ __forceinline__ void fma2(ull& d, ull a, ull b) {
    asm("fma.rn.f32x2 %0, %1, %2, %0;" : "+l"(d) : "l"(a), "l"(b));
}
__device__ __forceinline__ float fhadd(ull v) {
    float lo, hi;
    asm("mov.b64 {%0, %1}, %2;" : "=f"(lo), "=f"(hi) : "l"(v));
    return lo + hi;
}

// ---- grid barrier: fire-and-forget RED arrival + poll the counter itself ----
// Counter is monotonic (never reset). After step k of an n-CTA barrier the
// counter equals n*k, which is the poll target. The last arrival's RED *is*
// the release — no separate release store, no second L2 round trip.
__device__ __forceinline__ void gbar(int id, unsigned target) {
    __syncthreads();
    if (threadIdx.x == 0) {
        asm volatile("red.release.gpu.global.add.u32 [%0], %1;"
                     :: "l"(&g_cnt[id * 32]), "r"(1u) : "memory");
        unsigned v;
        do {
            asm volatile("ld.acquire.gpu.global.u32 %0, [%1];"
                         : "=r"(v) : "l"(&g_cnt[id * 32]) : "memory");
        } while ((int)(v - target) < 0);
    }
    __syncthreads();
}

// ---------- fused init + embedding gathers (single launch) ----------
__global__ void k_prep(const int* __restrict__ pre, const int* __restrict__ post,
                       const int* __restrict__ trg, const float* __restrict__ emb) {
    int blk = blockIdx.x;
    if (blk < 2048) {
        int g = blk >> 10;
        int bs = blk & 1023;
        int tok = (g ? post : pre)[bs];
        const float4* src = (const float4*)(emb + (size_t)tok * E_);
        float4* dst = (float4*)(&g_x[g][bs][0]);
        dst[threadIdx.x] = src[threadIdx.x];
    } else if (blk < 2048 + B_ * T_) {
        int r = blk - 2048;
        int b = r / T_, t = r % T_;
        int tok = (t == 0) ? pre[b * S_ + S_ - 1] : trg[b * T_ + t - 1];
        const float4* src = (const float4*)(emb + (size_t)tok * E_);
        float4* dst = (float4*)(&g_edec[b][t][0]);
        dst[threadIdx.x] = src[threadIdx.x];
    } else {
        for (int i = threadIdx.x; i < 512; i += 128) g_cnt[i] = 0;
    }
}

// --------------- scalar GEMM body: C[M,N] = A[M,K] @ W[N,K]^T + bias ---------------
__device__ __forceinline__ void gemm_body(const float* __restrict__ A, int lda,
                                          const float* __restrict__ W, int ldw,
                                          const float* __restrict__ bias,
                                          float* __restrict__ C, int ldc, int K,
                                          int m0, int n0) {
    __shared__ float As[16][68];
    __shared__ float Ws[16][68];
    int tid = threadIdx.x;
    int tx = tid & 15, ty = tid >> 4;
    int lr = tid >> 2;
    int lk = (tid & 3) * 4;
    float acc[4][4] = {};
    for (int k0 = 0; k0 < K; k0 += 16) {
        float4 av = *(const float4*)&A[(size_t)(m0 + lr) * lda + k0 + lk];
        float4 wv = *(const float4*)&W[(size_t)(n0 + lr) * ldw + k0 + lk];
        __syncthreads();
        As[lk + 0][lr] = av.x; As[lk + 1][lr] = av.y; As[lk + 2][lr] = av.z; As[lk + 3][lr] = av.w;
        Ws[lk + 0][lr] = wv.x; Ws[lk + 1][lr] = wv.y; Ws[lk + 2][lr] = wv.z; Ws[lk + 3][lr] = wv.w;
        __syncthreads();
#pragma unroll
        for (int kk = 0; kk < 16; kk++) {
            float4 a4 = *(const float4*)&As[kk][ty * 4];
            float4 w4 = *(const float4*)&Ws[kk][tx * 4];
            acc[0][0] = fmaf(a4.x, w4.x, acc[0][0]); acc[0][1] = fmaf(a4.x, w4.y, acc[0][1]);
            acc[0][2] = fmaf(a4.x, w4.z, acc[0][2]); acc[0][3] = fmaf(a4.x, w4.w, acc[0][3]);
            acc[1][0] = fmaf(a4.y, w4.x, acc[1][0]); acc[1][1] = fmaf(a4.y, w4.y, acc[1][1]);
            acc[1][2] = fmaf(a4.y, w4.z, acc[1][2]); acc[1][3] = fmaf(a4.y, w4.w, acc[1][3]);
            acc[2][0] = fmaf(a4.z, w4.x, acc[2][0]); acc[2][1] = fmaf(a4.z, w4.y, acc[2][1]);
            acc[2][2] = fmaf(a4.z, w4.z, acc[2][2]); acc[2][3] = fmaf(a4.z, w4.w, acc[2][3]);
            acc[3][0] = fmaf(a4.w, w4.x, acc[3][0]); acc[3][1] = fmaf(a4.w, w4.y, acc[3][1]);
            acc[3][2] = fmaf(a4.w, w4.z, acc[3][2]); acc[3][3] = fmaf(a4.w, w4.w, acc[3][3]);
        }
    }
    float4 b4 = *(const float4*)&bias[n0 + tx * 4];
#pragma unroll
    for (int i = 0; i < 4; i++) {
        float4 o = make_float4(acc[i][0] + b4.x, acc[i][1] + b4.y,
                               acc[i][2] + b4.z, acc[i][3] + b4.w);
        *(float4*)&C[(size_t)(m0 + ty * 4 + i) * ldc + n0 + tx * 4] = o;
    }
}

__global__ __launch_bounds__(256) void k_gemm(const float* __restrict__ A, int lda,
                                              const float* __restrict__ W, int ldw,
                                              const float* __restrict__ bias,
                                              float* __restrict__ C, int ldc, int K) {
    gemm_body(A, lda, W, ldw, bias, C, ldc, K, blockIdx.y * 64, blockIdx.x * 64);
}

__global__ __launch_bounds__(256) void k_gemm2(const float* __restrict__ A0, const float* __restrict__ W0,
                                               const float* __restrict__ b0, float* __restrict__ C0,
                                               const float* __restrict__ A1, const float* __restrict__ W1,
                                               const float* __restrict__ b1, float* __restrict__ C1) {
    const float* A = blockIdx.z ? A1 : A0;
    const float* W = blockIdx.z ? W1 : W0;
    const float* bias = blockIdx.z ? b1 : b0;
    float* C = blockIdx.z ? C1 : C0;
    gemm_body(A, E_, W, E_, bias, C, H3_, E_, blockIdx.y * 64, blockIdx.x * 64);
}

// ------------- w_eff two-stage -------------
__global__ void k_weffp(const float* __restrict__ fcW, const float* __restrict__ outW) {
    int j4 = (blockIdx.x & 3) * 128 + threadIdx.x;
    int kb = blockIdx.x >> 2;
    float4 acc = make_float4(0.f, 0.f, 0.f, 0.f);
    for (int i = kb * 64; i < kb * 64 + 64; i++) {
        float ov = __ldg(&outW[i]);
        float4 w = *(const float4*)&fcW[(size_t)i * D_ + j4 * 4];
        acc.x = fmaf(ov, w.x, acc.x); acc.y = fmaf(ov, w.y, acc.y);
        acc.z = fmaf(ov, w.z, acc.z); acc.w = fmaf(ov, w.w, acc.w);
    }
    *(float4*)&g_weffp[kb][j4 * 4] = acc;
}

__global__ void k_weff2(const float* __restrict__ outW, const float* __restrict__ fcb,
                        const float* __restrict__ outb) {
    int j = blockIdx.x * 256 + threadIdx.x;
    float v = 0.f;
#pragma unroll
    for (int kb = 0; kb < 32; kb++) v += g_weffp[kb][j];
    g_weff[j] = v;
    if (blockIdx.x == 0) {
        __shared__ float red[256];
        float a = 0.f;
        for (int i = threadIdx.x; i < D_; i += 256) a = fmaf(outW[i], fcb[i], a);
        red[threadIdx.x] = a; __syncthreads();
        for (int off = 128; off; off >>= 1) {
            if (threadIdx.x < off) red[threadIdx.x] += red[threadIdx.x + off];
            __syncthreads();
        }
        if (threadIdx.x == 0) g_beff[0] = outb[0] + red[0];
    }
}

// ------------------ persistent encoder: all 128 GRU steps ------------------
__global__ __launch_bounds__(256)
void k_enc(const float* __restrict__ Whh_pre, const float* __restrict__ bhh_pre,
           const float* __restrict__ Whh_post, const float* __restrict__ bhh_post) {
    extern __shared__ float sm[];
    float* wsm  = sm;                          // [3][8][PAD_]
    float* hs   = sm + 3 * 8 * PAD_;           // [8][PAD_]
    float* part = hs + 8 * PAD_;               // [3][8][8][4]
    int g = blockIdx.x >> 6, blk = blockIdx.x & 63;
    const float* Whh = g ? Whh_post : Whh_pre;
    const float* bhh = g ? bhh_post : bhh_pre;
    int t = threadIdx.x, b = t & 7, jl = (t >> 3) & 7, ks = t >> 6;
    int j = blk * 8 + jl;

    for (int i = t; i < 3 * 8 * 512; i += 256) {
        int gate = i >> 12, rem = i & 4095, jj = rem >> 9, k = rem & 511;
        wsm[(gate * 8 + jj) * PAD_ + k] = Whh[((size_t)(gate * 512 + blk * 8 + jj)) * 512 + k];
    }
    for (int i = t; i < 8 * PAD_; i += 256) hs[i] = 0.0f;
    float br = 0.f, bz = 0.f, bn = 0.f;
    if (ks == 0) { br = bhh[j]; bz = bhh[512 + j]; bn = bhh[1024 + j]; }
    __syncthreads();

    for (int s = 0; s < S_; s++) {
        float gir = 0.f, giz = 0.f, gin = 0.f;
        if (ks == 0) {
            gir = __ldg(&g_gi[g][b][s][j]);
            giz = __ldg(&g_gi[g][b][s][512 + j]);
            gin = __ldg(&g_gi[g][b][s][1024 + j]);
        }
        const ulonglong2* hb = (const ulonglong2*)&hs[b * PAD_ + ks * 128];
        const ulonglong2* wr = (const ulonglong2*)&wsm[(0 * 8 + jl) * PAD_ + ks * 128];
        const ulonglong2* wz = (const ulonglong2*)&wsm[(1 * 8 + jl) * PAD_ + ks * 128];
        const ulonglong2* wn = (const ulonglong2*)&wsm[(2 * 8 + jl) * PAD_ + ks * 128];
        ull ar2 = 0, az2 = 0, an2 = 0;
#pragma unroll 8
        for (int k = 0; k < 32; k++) {
            ulonglong2 h2 = hb[k];
            ulonglong2 r2 = wr[k], z2 = wz[k], n2 = wn[k];
            fma2(ar2, h2.x, r2.x); fma2(ar2, h2.y, r2.y);
            fma2(az2, h2.x, z2.x); fma2(az2, h2.y, z2.y);
            fma2(an2, h2.x, n2.x); fma2(an2, h2.y, n2.y);
        }
        part[((0 * 8 + jl) * 8 + b) * 4 + ks] = fhadd(ar2);
        part[((1 * 8 + jl) * 8 + b) * 4 + ks] = fhadd(az2);
        part[((2 * 8 + jl) * 8 + b) * 4 + ks] = fhadd(an2);
        __syncthreads();
        if (ks == 0) {
            float* p0 = &part[((0 * 8 + jl) * 8 + b) * 4];
            float* p1 = &part[((1 * 8 + jl) * 8 + b) * 4];
            float* p2 = &part[((2 * 8 + jl) * 8 + b) * 4];
            float ghr = p0[0] + p0[1] + p0[2] + p0[3] + br;
            float ghz = p1[0] + p1[1] + p1[2] + p1[3] + bz;
            float ghn = p2[0] + p2[1] + p2[2] + p2[3] + bn;
            float r = sigm(gir + ghr);
            float z = sigm(giz + ghz);
            float n = tanhf(gin + r * ghn);
            float h2 = (1.0f - z) * n + z * hs[b * PAD_ + j];
            __stcg(&g_henc[g][s & 1][b * 512 + j], h2);
            g_enc_out[b][g * 128 + s][j] = h2;
        }
        gbar(g, 64u * (unsigned)(s + 1));
        const float4* src = (const float4*)&g_henc[g][s & 1][0];
        for (int i = t; i < 1024; i += 256) {
            float4 v = __ldcg(src + i);
            int base = i * 4;
            float* d = &hs[(base >> 9) * PAD_ + (base & 511)];
            d[0] = v.x; d[1] = v.y; d[2] = v.z; d[3] = v.w;
        }
        __syncthreads();
    }
}

// -------- hidden0 = tanh([pre_h|post_h] @ fc_enc_W^T + b) --------
__global__ __launch_bounds__(256) void k_hidden(const float* __restrict__ W,
                                                const float* __restrict__ bias) {
    __shared__ float hcat[8][1028];
    int t = threadIdx.x;
    for (int i = t; i < 8 * 1024; i += 256) {
        int b = i >> 10, k = i & 1023;
        hcat[b][k] = (k < 512) ? g_henc[0][1][b * 512 + k] : g_henc[1][1][b * 512 + k - 512];
    }
    __syncthreads();
    int b = t & 7, d = blockIdx.x * 32 + (t >> 3);
    const float4* w = (const float4*)(W + (size_t)d * 1024);
    const float4* x = (const float4*)&hcat[b][0];
    float acc = 0.f;
#pragma unroll 4
    for (int k = 0; k < 256; k++) {
        float4 w4 = w[k], x4 = x[k];
        acc = fmaf(w4.x, x4.x, acc); acc = fmaf(w4.y, x4.y, acc);
        acc = fmaf(w4.z, x4.z, acc); acc = fmaf(w4.w, x4.w, acc);
    }
    g_hid0[b][d] = tanhf(acc + bias[d]);
}

// --------------- enc_dot[b][l] = enc_out[b][l] . w_eff[0:512] ---------------
__global__ void k_encdot() {
    int r = blockIdx.x * 8 + (threadIdx.x >> 5);
    int lane = threadIdx.x & 31;
    int b = r >> 8, l = r & 255;
    const float4* e = (const float4*)&g_enc_out[b][l][0];
    const float4* w = (const float4*)&g_weff[0];
    float v = 0.f;
#pragma unroll
    for (int c = 0; c < 4; c++) {
        int f = lane + 32 * c;
        float4 e4 = e[f], w4 = w[f];
        v = fmaf(e4.x, w4.x, v); v = fmaf(e4.y, w4.y, v);
        v = fmaf(e4.z, w4.z, v); v = fmaf(e4.w, w4.w, v);
    }
    v = warp_sum(v);
    if (lane == 0) g_enc_dot[b][l] = v;
}

// ------------------ persistent decoder: all 24 steps ------------------
__global__ __launch_bounds__(256)
void k_dec(const float* __restrict__ Wih, const float* __restrict__ Whh,
           const float* __restrict__ bhh, const float* __restrict__ attnW,
           const float* __restrict__ attnv) {
    extern __shared__ float sm[];
    float* whh_sm  = sm;                              // [3][4][PAD_]
    float* wih_sm  = whh_sm + 3 * 4 * PAD_;
    float* whid_sm = wih_sm + 3 * 4 * PAD_;           // [4][PAD_]
    float* hs      = whid_sm + 4 * PAD_;              // [8][PAD_]
    float* ws      = hs + 8 * PAD_;                   // [8][PAD_]
    float* ep_sm   = ws + 8 * PAD_;                   // [16][512]
    float* eo_sm   = ep_sm + 16 * 512;                // [256][33]
    float* vs_sm   = eo_sm + 256 * 33;                // [512]
    float* q_sm    = vs_sm + 512;                     // [512]
    float* red     = q_sm + 512;                      // [256]
    float* aa      = red + 256;                       // [256]
    float* part    = aa + 256;                        // [1536]
    int t = threadIdx.x;
    int blk = blockIdx.x;
    int b8 = t & 7, jl4 = (t >> 3) & 3, ks8 = t >> 5;
    int myb = blk >> 4, hch = (blk & 15) * 32;
    int j = blk * 4 + jl4;

    for (int i = t; i < 3 * 4 * 512; i += 256) {
        int gate = i >> 11, rem = i & 2047, jj = rem >> 9, k = rem & 511;
        int row = gate * 512 + blk * 4 + jj;
        whh_sm[(gate * 4 + jj) * PAD_ + k] = Whh[(size_t)row * 512 + k];
        wih_sm[(gate * 4 + jj) * PAD_ + k] = Wih[(size_t)row * 1024 + 512 + k];
    }
    for (int i = t; i < 4 * 512; i += 256)
        whid_sm[(i >> 9) * PAD_ + (i & 511)] = attnW[(size_t)(blk * 4 + (i >> 9)) * 1024 + (i & 511)];
    for (int i = t; i < 8 * 512; i += 256)
        hs[(i >> 9) * PAD_ + (i & 511)] = ((const float*)g_hid0)[i];
    for (int i = t; i < 16 * 512; i += 256) {
        int row = i >> 9, f = i & 511;
        int r = blk * 16 + row, bb = r >> 8, l = r & 255;
        ep_sm[i] = g_enc_proj[bb][l][f];
    }
    for (int i = t; i < 256 * 32; i += 256) {
        int l = i >> 5, hh = i & 31;
        eo_sm[l * 33 + hh] = g_enc_out[myb][l][hch + hh];
    }
    for (int i = t; i < 512; i += 256) vs_sm[i] = attnv[i];
    float bhr = 0.f, bhz = 0.f, bhn = 0.f;
    if (ks8 == 0) { bhr = bhh[j]; bhz = bhh[512 + j]; bhn = bhh[1024 + j]; }
    __syncthreads();

    unsigned genF = 0, genG = 0;
    for (int tt = 0; tt < T_; tt++) {
        float gir = 0.f, giz = 0.f, gin = 0.f;
        if (ks8 == 0) {
            gir = __ldg(&g_gie[b8][tt][j]);
            giz = __ldg(&g_gie[b8][tt][512 + j]);
            gin = __ldg(&g_gie[b8][tt][1024 + j]);
        }
        // ---- A: q[b][d] = h . W_hid[d] ----
        {
            const ulonglong2* hb = (const ulonglong2*)&hs[b8 * PAD_ + ks8 * 64];
            const ulonglong2* wd = (const ulonglong2*)&whid_sm[jl4 * PAD_ + ks8 * 64];
            ull acc2 = 0;
#pragma unroll
            for (int k = 0; k < 16; k++) {
                ulonglong2 h2 = hb[k], w2 = wd[k];
                fma2(acc2, h2.x, w2.x); fma2(acc2, h2.y, w2.y);
            }
            part[(jl4 * 8 + b8) * 8 + ks8] = fhadd(acc2);
            __syncthreads();
            if (ks8 == 0) {
                float* p = &part[(jl4 * 8 + b8) * 8];
                __stcg(&g_q[b8][j], p[0] + p[1] + p[2] + p[3] + p[4] + p[5] + p[6] + p[7]);
            }
        }
        genF++; gbar(2, 128u * genF);
        // ---- B: scores[b][l]; stage q[myb] into smem once ----
        {
            for (int i = t; i < 128; i += 256) {
                float4 v = __ldcg(((const float4*)&g_q[myb][0]) + i);
                *(float4*)&q_sm[i * 4] = v;
            }
            __syncthreads();
            int w = t >> 5, lane = t & 31;
#pragma unroll
            for (int rr = 0; rr < 2; rr++) {
                int row = w * 2 + rr;
                int r = blk * 16 + row;
                int bb = r >> 8, l = r & 255;
                const float4* ep = (const float4*)&ep_sm[row * 512];
                const float4* qp = (const float4*)q_sm;
                const float4* vp = (const float4*)vs_sm;
                float acc = 0.f;
#pragma unroll
                for (int c = 0; c < 4; c++) {
                    int f = lane + 32 * c;
                    float4 e4 = ep[f], v4 = vp[f], q4 = qp[f];
                    acc = fmaf(tanhf(e4.x + q4.x), v4.x, acc);
                    acc = fmaf(tanhf(e4.y + q4.y), v4.y, acc);
                    acc = fmaf(tanhf(e4.z + q4.z), v4.z, acc);
                    acc = fmaf(tanhf(e4.w + q4.w), v4.w, acc);
                }
                acc = warp_sum(acc);
                if (lane == 0) { __stcg(&g_scores[bb][l], acc); }
            }
        }
        genG++; gbar(8 + myb, 16u * genG);
        // ---- C: softmax over L for myb + weighted chunk ----
        {
            float s = __ldcg(&g_scores[myb][t]);
            red[t] = s; __syncthreads();
            for (int off = 128; off; off >>= 1) {
                if (t < off) red[t] = fmaxf(red[t], red[t + off]);
                __syncthreads();
            }
            float mx = red[0]; __syncthreads();
            float e = expf(s - mx);
            red[t] = e; __syncthreads();
            for (int off = 128; off; off >>= 1) {
                if (t < off) red[t] += red[t + off];
                __syncthreads();
            }
            aa[t] = e / red[0];
            __syncthreads();
            int hh = t & 31, ls = t >> 5;
            float acc = 0.f;
            int l0 = ls * 32;
#pragma unroll 8
            for (int l = l0; l < l0 + 32; l++)
                acc = fmaf(aa[l], eo_sm[l * 33 + hh], acc);
            part[ls * 32 + hh] = acc;
            __syncthreads();
            if (t < 32) {
                float v = 0.f;
#pragma unroll
                for (int q = 0; q < 8; q++) v += part[q * 32 + t];
                __stcg(&g_wall[tt][myb][hch + t], v);
            }
        }
        genF++; gbar(2, 128u * genF);
        // ---- D: GRU ----
        {
            const float4* src = (const float4*)&g_wall[tt][0][0];
            for (int i = t; i < 1024; i += 256) {
                float4 v = __ldcg(src + i);
                int base = i * 4;
                float* d = &ws[(base >> 9) * PAD_ + (base & 511)];
                d[0] = v.x; d[1] = v.y; d[2] = v.z; d[3] = v.w;
            }
            __syncthreads();
            const ulonglong2* hb = (const ulonglong2*)&hs[b8 * PAD_ + ks8 * 64];
            const ulonglong2* wb = (const ulonglong2*)&ws[b8 * PAD_ + ks8 * 64];
            const ulonglong2* whr = (const ulonglong2*)&whh_sm[(0 * 4 + jl4) * PAD_ + ks8 * 64];
            const ulonglong2* whz = (const ulonglong2*)&whh_sm[(1 * 4 + jl4) * PAD_ + ks8 * 64];
            const ulonglong2* whn = (const ulonglong2*)&whh_sm[(2 * 4 + jl4) * PAD_ + ks8 * 64];
            const ulonglong2* wir = (const ulonglong2*)&wih_sm[(0 * 4 + jl4) * PAD_ + ks8 * 64];
            const ulonglong2* wiz = (const ulonglong2*)&wih_sm[(1 * 4 + jl4) * PAD_ + ks8 * 64];
            const ulonglong2* win = (const ulonglong2*)&wih_sm[(2 * 4 + jl4) * PAD_ + ks8 * 64];
            ull ahr = 0, ahz = 0, ahn = 0, air = 0, aiz = 0, ain = 0;
#pragma unroll 4
            for (int k = 0; k < 16; k++) {
                ulonglong2 h2 = hb[k], w2 = wb[k];
                ulonglong2 r2 = whr[k], z2 = whz[k], n2 = whn[k];
                ulonglong2 a2 = wir[k], c2 = wiz[k], d2 = win[k];
                fma2(ahr, h2.x, r2.x); fma2(ahr, h2.y, r2.y);
                fma2(ahz, h2.x, z2.x); fma2(ahz, h2.y, z2.y);
                fma2(ahn, h2.x, n2.x); fma2(ahn, h2.y, n2.y);
                fma2(air, w2.x, a2.x); fma2(air, w2.y, a2.y);
                fma2(aiz, w2.x, c2.x); fma2(aiz, w2.y, c2.y);
                fma2(ain, w2.x, d2.x); fma2(ain, w2.y, d2.y);
            }
            part[(0 * 4 + jl4) * 64 + b8 * 8 + ks8] = fhadd(ahr);
            part[(1 * 4 + jl4) * 64 + b8 * 8 + ks8] = fhadd(ahz);
            part[(2 * 4 + jl4) * 64 + b8 * 8 + ks8] = fhadd(ahn);
            part[(3 * 4 + jl4) * 64 + b8 * 8 + ks8] = fhadd(air);
            part[(4 * 4 + jl4) * 64 + b8 * 8 + ks8] = fhadd(aiz);
            part[(5 * 4 + jl4) * 64 + b8 * 8 + ks8] = fhadd(ain);
            __syncthreads();
            if (ks8 == 0) {
                float sum[6];
#pragma unroll
                for (int m = 0; m < 6; m++) {
                    float* p = &part[(m * 4 + jl4) * 64 + b8 * 8];
                    sum[m] = p[0] + p[1] + p[2] + p[3] + p[4] + p[5] + p[6] + p[7];
                }
                float ghr = sum[0] + bhr, ghz = sum[1] + bhz, ghn = sum[2] + bhn;
                float r = sigm((gir + sum[3]) + ghr);
                float z = sigm((giz + sum[4]) + ghz);
                float n = tanhf((gin + sum[5]) + r * ghn);
                float h2 = (1.0f - z) * n + z * hs[b8 * PAD_ + j];
                __stcg(&g_hidbuf[(tt + 1) & 1][b8][j], h2);
                g_h2all[tt][b8][j] = h2;
            }
        }
        genF++; gbar(2, 128u * genF);
        if (tt + 1 < T_) {
            const float4* src = (const float4*)&g_hidbuf[(tt + 1) & 1][0][0];
            for (int i = t; i < 1024; i += 256) {
                float4 v = __ldcg(src + i);
                int base = i * 4;
                float* d = &hs[(base >> 9) * PAD_ + (base & 511)];
                d[0] = v.x; d[1] = v.y; d[2] = v.z; d[3] = v.w;
            }
            __syncthreads();
        }
    }
}

// ------------------------------ final logits ------------------------------
__global__ void k_logits(float* __restrict__ out) {
    int b = blockIdx.x / T_, tt = blockIdx.x % T_;
    int t = threadIdx.x;
    __shared__ float red[256];
    float acc = 0.f;
#pragma unroll
    for (int c = 0; c < 2; c++) {
        int h = t + c * 256;
        acc = fmaf(g_wall[tt][b][h],  g_weff[512 + h],  acc);
        acc = fmaf(g_h2all[tt][b][h], g_weff[1024 + h], acc);
        acc = fmaf(g_edec[b][tt][h],  g_weff[1536 + h], acc);
    }
    red[t] = acc; __syncthreads();
    for (int off = 128; off; off >>= 1) {
        if (t < off) red[t] += red[t + off];
        __syncthreads();
    }
    float sc = red[0] + g_beff[0];
    float val = g_enc_dot[b][t] + sc;
    int base = (b * T_ + tt) * 128;
    if (t < 128) out[base + t] = val;
    else out[B_ * T_ * 128 + base + t - 128] = val;
}

// ------------------------------ host launch ------------------------------
extern "C" void kernel_launch(void* const* d_in, const int* in_sizes, int n_in,
                              void* d_out, int out_size) {
    const int*   pre      = (const int*)d_in[0];
    const int*   post     = (const int*)d_in[1];
    const int*   trg      = (const int*)d_in[2];
    const float* emb      = (const float*)d_in[3];
    const float* Wih_pre  = (const float*)d_in[4];
    const float* Whh_pre  = (const float*)d_in[5];
    const float* bih_pre  = (const float*)d_in[6];
    const float* bhh_pre  = (const float*)d_in[7];
    const float* Wih_post = (const float*)d_in[8];
    const float* Whh_post = (const float*)d_in[9];
    const float* bih_post = (const float*)d_in[10];
    const float* bhh_post = (const float*)d_in[11];
    const float* fc_enc_W = (const float*)d_in[12];
    const float* fc_enc_b = (const float*)d_in[13];
    const float* attn_W   = (const float*)d_in[14];
    const float* attn_b   = (const float*)d_in[15];
    const float* attn_v   = (const float*)d_in[16];
    const float* Wih_dec  = (const float*)d_in[17];
    const float* Whh_dec  = (const float*)d_in[18];
    const float* bih_dec  = (const float*)d_in[19];
    const float* bhh_dec  = (const float*)d_in[20];
    const float* fc_hid_W = (const float*)d_in[21];
    const float* fc_hid_b = (const float*)d_in[22];
    const float* fc_out_W = (const float*)d_in[23];
    const float* fc_out_b = (const float*)d_in[24];
    float* out = (float*)d_out;

    float *p_x, *p_gi, *p_edec, *p_gie, *p_enc_out, *p_enc_proj;
    cudaGetSymbolAddress((void**)&p_x, g_x);
    cudaGetSymbolAddress((void**)&p_gi, g_gi);
    cudaGetSymbolAddress((void**)&p_edec, g_edec);
    cudaGetSymbolAddress((void**)&p_gie, g_gie);
    cudaGetSymbolAddress((void**)&p_enc_out, g_enc_out);
    cudaGetSymbolAddress((void**)&p_enc_proj, g_enc_proj);

    const int ENC_SMEM = (3 * 8 * PAD_ + 8 * PAD_ + 768) * 4;
    const int DEC_SMEM = (3 * 4 * PAD_ * 2 + 4 * PAD_ + 8 * PAD_ * 2 +
                          16 * 512 + 256 * 33 + 512 + 512 + 256 + 256 + 1536) * 4;
    cudaFuncSetAttribute(k_enc, cudaFuncAttributeMaxDynamicSharedMemorySize, ENC_SMEM);
    cudaFuncSetAttribute(k_dec, cudaFuncAttributeMaxDynamicSharedMemorySize, DEC_SMEM);

    // launch order: k_enc is our 4th launch (the ncu capture slot)
    k_prep<<<2048 + B_ * T_ + 1, 128>>>(pre, post, trg, emb);        // 1
    k_gemm2<<<dim3(24, 16, 2), 256>>>(p_x, Wih_pre, bih_pre, p_gi,   // 2
                                      p_x + (size_t)B_ * S_ * E_, Wih_post, bih_post,
                                      p_gi + (size_t)B_ * S_ * H3_);
    k_gemm<<<dim3(24, 3), 256>>>(p_edec, E_, Wih_dec, 1024, bih_dec, // 3
                                 p_gie, H3_, E_);
    k_enc<<<128, 256, ENC_SMEM>>>(Whh_pre, bhh_pre, Whh_post, bhh_post);  // 4 <- profiled

    k_weffp<<<128, 128>>>(fc_hid_W, fc_out_W);
    k_weff2<<<8, 256>>>(fc_out_W, fc_hid_b, fc_out_b);
    k_hidden<<<16, 256>>>(fc_enc_W, fc_enc_b);
    k_gemm<<<dim3(8, 32), 256>>>(p_enc_out, H_, attn_W + H_, 1024, attn_b, p_enc_proj, H_, H_);
    k_encdot<<<256, 256>>>();

    k_dec<<<128, 256, DEC_SMEM>>>(Wih_dec, Whh_dec, bhh_dec, attn_W, attn_v);

    k_logits<<<B_ * T_, 256>>>(out);
}